// round 3
// baseline (speedup 1.0000x reference)
#include <cuda_runtime.h>

#define NTOK 49
#define NHEAD 12
#define HD 32
#define CDIM 384
#define QKVDIM 1152
#define BWIN 8192
#define NWMASK 1024
#define MROWS (BWIN * NTOK)   // 401408

// Scratch (device globals: the sanctioned no-alloc scratch path)
__device__ float g_qkv[(size_t)MROWS * QKVDIM];     // [B_, N, 3, H, hd] flattened = GEMM output
__device__ float g_att[(size_t)MROWS * CDIM];       // [B_, N, C] pre-projection
__device__ float g_bias[NHEAD * NTOK * NTOK];       // [H, N, N] relative position bias

__device__ __forceinline__ unsigned f2tf(float f) {
    unsigned r;
    asm("cvt.rna.tf32.f32 %0, %1;" : "=r"(r) : "f"(f));
    return r;
}

__device__ __forceinline__ void mma8(float* c, const unsigned* a, const unsigned* b) {
    asm volatile(
        "mma.sync.aligned.m16n8k8.row.col.f32.tf32.tf32.f32 "
        "{%0,%1,%2,%3}, {%4,%5,%6,%7}, {%8,%9}, {%0,%1,%2,%3};\n"
        : "+f"(c[0]), "+f"(c[1]), "+f"(c[2]), "+f"(c[3])
        : "r"(a[0]), "r"(a[1]), "r"(a[2]), "r"(a[3]), "r"(b[0]), "r"(b[1]));
}

// C[M,N] = A[M,K] @ B[K,N]; fp32 in/out, tf32 tensor-core compute.
// Requires M%128==0, N%128==0, K%16==0 (true for both call sites).
__global__ void gemm_tf32(const float* __restrict__ A, const float* __restrict__ B,
                          float* __restrict__ C, int N, int K) {
    __shared__ unsigned As[2][128 * 20];   // [m][k], stride 20 -> conflict-free A-frag loads
    __shared__ unsigned Bs[2][16 * 136];   // [k][n], stride 136 -> conflict-free B-frag loads

    const int t    = threadIdx.x;
    const int lane = t & 31;
    const int w    = t >> 5;
    const int wm   = w & 1;        // 2 warp-rows (64 M each)
    const int wn   = w >> 1;       // 4 warp-cols (32 N each)
    const int g    = lane >> 2;    // groupID
    const int tg   = lane & 3;     // threadID_in_group
    const int mBase = blockIdx.y << 7;
    const int nBase = blockIdx.x << 7;

    // global->smem tiling: A tile 128x16, B tile 16x128, float4 per thread x2
    const int ar = t >> 2,  ac = (t & 3) << 2;    // A: 4 thr/row
    const int br = t >> 5,  bc = lane << 2;       // B: 32 thr/row

    const float* Ap = A + (size_t)(mBase + ar) * K + ac;
    const float* Bp = B + (size_t)br * N + nBase + bc;

    float4 a0r = *(const float4*)Ap;
    float4 a1r = *(const float4*)(Ap + (size_t)64 * K);
    float4 b0r = *(const float4*)Bp;
    float4 b1r = *(const float4*)(Bp + (size_t)8 * N);

    float acc[4][4][4];
#pragma unroll
    for (int i = 0; i < 4; ++i)
#pragma unroll
        for (int j = 0; j < 4; ++j)
#pragma unroll
            for (int q = 0; q < 4; ++q) acc[i][j][q] = 0.f;

    const int NT = K >> 4;

    {   // stage tile 0 (convert to tf32 at store)
        unsigned* as = As[0]; unsigned* bs = Bs[0];
        *(uint4*)&as[ar * 20 + ac]        = make_uint4(f2tf(a0r.x), f2tf(a0r.y), f2tf(a0r.z), f2tf(a0r.w));
        *(uint4*)&as[(ar + 64) * 20 + ac] = make_uint4(f2tf(a1r.x), f2tf(a1r.y), f2tf(a1r.z), f2tf(a1r.w));
        *(uint4*)&bs[br * 136 + bc]       = make_uint4(f2tf(b0r.x), f2tf(b0r.y), f2tf(b0r.z), f2tf(b0r.w));
        *(uint4*)&bs[(br + 8) * 136 + bc] = make_uint4(f2tf(b1r.x), f2tf(b1r.y), f2tf(b1r.z), f2tf(b1r.w));
    }
    __syncthreads();

    for (int kt = 0; kt < NT; ++kt) {
        const int buf = kt & 1;
        if (kt + 1 < NT) {  // prefetch next tile into registers
            const float* Ap2 = Ap + (kt + 1) * 16;
            const float* Bp2 = Bp + (size_t)(kt + 1) * 16 * N;
            a0r = *(const float4*)Ap2;
            a1r = *(const float4*)(Ap2 + (size_t)64 * K);
            b0r = *(const float4*)Bp2;
            b1r = *(const float4*)(Bp2 + (size_t)8 * N);
        }
        const unsigned* as = As[buf];
        const unsigned* bs = Bs[buf];
#pragma unroll
        for (int ks = 0; ks < 16; ks += 8) {
            unsigned af[4][4], bf[4][2];
#pragma unroll
            for (int mt = 0; mt < 4; ++mt) {
                const int r = wm * 64 + mt * 16 + g;
                af[mt][0] = as[r * 20 + ks + tg];
                af[mt][1] = as[(r + 8) * 20 + ks + tg];
                af[mt][2] = as[r * 20 + ks + tg + 4];
                af[mt][3] = as[(r + 8) * 20 + ks + tg + 4];
            }
#pragma unroll
            for (int nt = 0; nt < 4; ++nt) {
                const int nc = wn * 32 + nt * 8 + g;
                bf[nt][0] = bs[(ks + tg) * 136 + nc];
                bf[nt][1] = bs[(ks + tg + 4) * 136 + nc];
            }
#pragma unroll
            for (int mt = 0; mt < 4; ++mt)
#pragma unroll
                for (int nt = 0; nt < 4; ++nt)
                    mma8(acc[mt][nt], af[mt], bf[nt]);
        }
        if (kt + 1 < NT) {  // stage prefetched tile into other buffer
            unsigned* asw = As[buf ^ 1]; unsigned* bsw = Bs[buf ^ 1];
            *(uint4*)&asw[ar * 20 + ac]        = make_uint4(f2tf(a0r.x), f2tf(a0r.y), f2tf(a0r.z), f2tf(a0r.w));
            *(uint4*)&asw[(ar + 64) * 20 + ac] = make_uint4(f2tf(a1r.x), f2tf(a1r.y), f2tf(a1r.z), f2tf(a1r.w));
            *(uint4*)&bsw[br * 136 + bc]       = make_uint4(f2tf(b0r.x), f2tf(b0r.y), f2tf(b0r.z), f2tf(b0r.w));
            *(uint4*)&bsw[(br + 8) * 136 + bc] = make_uint4(f2tf(b1r.x), f2tf(b1r.y), f2tf(b1r.z), f2tf(b1r.w));
        }
        __syncthreads();
    }

#pragma unroll
    for (int mt = 0; mt < 4; ++mt) {
#pragma unroll
        for (int nt = 0; nt < 4; ++nt) {
            const int r0 = mBase + wm * 64 + mt * 16 + g;
            const int c0 = nBase + wn * 32 + nt * 8 + tg * 2;
            *(float2*)&C[(size_t)r0 * N + c0]       = make_float2(acc[mt][nt][0], acc[mt][nt][1]);
            *(float2*)&C[(size_t)(r0 + 8) * N + c0] = make_float2(acc[mt][nt][2], acc[mt][nt][3]);
        }
    }
}

// Precompute relative-position bias: g_bias[h][i][j] = rpb_table[rpi(i,j)*12 + h]
// rpi(i,j) = 13*((i%7)-(j%7)+6) + (i/7)-(j/7)+6   (from tf.meshgrid 'xy' semantics)
__global__ void bias_kernel(const float* __restrict__ rpb) {
    int idx = blockIdx.x * 256 + threadIdx.x;
    if (idx >= NHEAD * NTOK * NTOK) return;
    int h = idx / (NTOK * NTOK);
    int r = idx % (NTOK * NTOK);
    int i = r / NTOK, j = r % NTOK;
    int rpi = 13 * ((i % 7) - (j % 7) + 6) + (i / 7) - (j / 7) + 6;
    g_bias[idx] = rpb[rpi * NHEAD + h];
}

// One CTA per (window b, head h). fp32 throughout.
__global__ __launch_bounds__(256)
void attn_kernel(const float* __restrict__ mask) {
    __shared__ float qs[NTOK * 33], ks[NTOK * 33], vs[NTOK * 33];
    __shared__ float ss[NTOK * NTOK];   // row stride 49: lane-consecutive -> conflict-free

    const int blk = blockIdx.x;
    const int b = blk / NHEAD;
    const int h = blk - b * NHEAD;

    const float* base = g_qkv + (size_t)b * NTOK * QKVDIM + h * HD;
    const float scale = 0.17677669529663687f;   // 32^-0.5

    for (int e = threadIdx.x; e < NTOK * HD; e += 256) {
        int n = e >> 5, d = e & 31;
        size_t o = (size_t)n * QKVDIM + d;
        qs[n * 33 + d] = base[o] * scale;
        ks[n * 33 + d] = base[o + CDIM];
        vs[n * 33 + d] = base[o + 2 * CDIM];
    }
    __syncthreads();

    const float* bh = g_bias + h * NTOK * NTOK;
    const float* mw = mask + (size_t)(b & (NWMASK - 1)) * NTOK * NTOK;   // b % 1024

    for (int p = threadIdx.x; p < NTOK * NTOK; p += 256) {
        int i = p / NTOK, j = p - i * NTOK;
        float a = 0.f;
#pragma unroll 8
        for (int d = 0; d < HD; ++d) a += qs[i * 33 + d] * ks[j * 33 + d];
        ss[p] = a + bh[p] + mw[p];
    }
    __syncthreads();

    // Warp-per-row softmax: 8 warps stride the 49 rows; lanes cover j with
    // shfl-butterfly reductions. All 256 threads active (vs 49 before).
    {
        const int w = threadIdx.x >> 5, lane = threadIdx.x & 31;
        for (int r = w; r < NTOK; r += 8) {
            float* row = ss + r * NTOK;
            float m = -3.4e38f;
            for (int j = lane; j < NTOK; j += 32) m = fmaxf(m, row[j]);
#pragma unroll
            for (int o = 16; o; o >>= 1) m = fmaxf(m, __shfl_xor_sync(0xffffffffu, m, o));
            float s = 0.f;
            for (int j = lane; j < NTOK; j += 32) { float e = __expf(row[j] - m); row[j] = e; s += e; }
#pragma unroll
            for (int o = 16; o; o >>= 1) s += __shfl_xor_sync(0xffffffffu, s, o);
            float inv = 1.f / s;
            for (int j = lane; j < NTOK; j += 32) row[j] *= inv;
        }
    }
    __syncthreads();

    float* ob = g_att + (size_t)b * NTOK * CDIM + h * HD;
    for (int p = threadIdx.x; p < NTOK * HD; p += 256) {
        int i = p >> 5, d = p & 31;
        float a = 0.f;
        const float* srow = ss + i * NTOK;
#pragma unroll 7
        for (int j = 0; j < NTOK; ++j) a += srow[j] * vs[j * 33 + d];
        ob[(size_t)i * CDIM + d] = a;
    }
}

extern "C" void kernel_launch(void* const* d_in, const int* in_sizes, int n_in,
                              void* d_out, int out_size) {
    // Match inputs by element count (all distinct) — robust to metadata ordering.
    const float *x = nullptr, *mask = nullptr, *wqkv = nullptr, *wproj = nullptr, *rpb = nullptr;
    for (int i = 0; i < n_in; ++i) {
        switch (in_sizes[i]) {
            case 154140672: x     = (const float*)d_in[i]; break;  // 401408*384
            case 2458624:   mask  = (const float*)d_in[i]; break;  // 1024*49*49
            case 442368:    wqkv  = (const float*)d_in[i]; break;  // 384*1152
            case 147456:    wproj = (const float*)d_in[i]; break;  // 384*384
            case 2028:      rpb   = (const float*)d_in[i]; break;  // 169*12
        }
    }

    float *qkv_p = nullptr, *att_p = nullptr;
    cudaGetSymbolAddress((void**)&qkv_p, g_qkv);
    cudaGetSymbolAddress((void**)&att_p, g_att);

    bias_kernel<<<(NHEAD * NTOK * NTOK + 255) / 256, 256>>>(rpb);

    // QKV projection: [401408,384] @ [384,1152]
    gemm_tf32<<<dim3(QKVDIM / 128, MROWS / 128), 256>>>(x, wqkv, qkv_p, QKVDIM, CDIM);

    // Per-(window, head) attention
    attn_kernel<<<BWIN * NHEAD, 256>>>(mask);

    // Output projection: [401408,384] @ [384,384] -> d_out
    gemm_tf32<<<dim3(CDIM / 128, MROWS / 128), 256>>>(att_p, wproj, (float*)d_out, CDIM, CDIM);
}

// round 4
// speedup vs baseline: 1.6043x; 1.6043x over previous
#include <cuda_runtime.h>

#define NTOK 49
#define NHEAD 12
#define HD 32
#define CDIM 384
#define QKVDIM 1152
#define BWIN 8192
#define NWMASK 1024
#define MROWS (BWIN * NTOK)   // 401408

__device__ float g_qkv[(size_t)MROWS * QKVDIM];     // QKV GEMM output
__device__ float g_att[(size_t)MROWS * CDIM];       // pre-projection attention output
__device__ float g_bias[NHEAD * NTOK * NTOK];       // [H, N, N] relative position bias

__device__ __forceinline__ unsigned f2tf(float f) {
    unsigned r;
    asm("cvt.rna.tf32.f32 %0, %1;" : "=r"(r) : "f"(f));
    return r;
}

__device__ __forceinline__ void mma8(float* c, const unsigned* a, const unsigned* b) {
    asm volatile(
        "mma.sync.aligned.m16n8k8.row.col.f32.tf32.tf32.f32 "
        "{%0,%1,%2,%3}, {%4,%5,%6,%7}, {%8,%9}, {%0,%1,%2,%3};\n"
        : "+f"(c[0]), "+f"(c[1]), "+f"(c[2]), "+f"(c[3])
        : "r"(a[0]), "r"(a[1]), "r"(a[2]), "r"(a[3]), "r"(b[0]), "r"(b[1]));
}

// ---------------- big GEMMs (unchanged from round 3 baseline) ----------------
__global__ void gemm_tf32(const float* __restrict__ A, const float* __restrict__ B,
                          float* __restrict__ C, int N, int K) {
    __shared__ unsigned As[2][128 * 20];
    __shared__ unsigned Bs[2][16 * 136];

    const int t    = threadIdx.x;
    const int lane = t & 31;
    const int w    = t >> 5;
    const int wm   = w & 1;
    const int wn   = w >> 1;
    const int g    = lane >> 2;
    const int tg   = lane & 3;
    const int mBase = blockIdx.y << 7;
    const int nBase = blockIdx.x << 7;

    const int ar = t >> 2,  ac = (t & 3) << 2;
    const int br = t >> 5,  bc = lane << 2;

    const float* Ap = A + (size_t)(mBase + ar) * K + ac;
    const float* Bp = B + (size_t)br * N + nBase + bc;

    float4 a0r = *(const float4*)Ap;
    float4 a1r = *(const float4*)(Ap + (size_t)64 * K);
    float4 b0r = *(const float4*)Bp;
    float4 b1r = *(const float4*)(Bp + (size_t)8 * N);

    float acc[4][4][4];
#pragma unroll
    for (int i = 0; i < 4; ++i)
#pragma unroll
        for (int j = 0; j < 4; ++j)
#pragma unroll
            for (int q = 0; q < 4; ++q) acc[i][j][q] = 0.f;

    const int NT = K >> 4;

    {
        unsigned* as = As[0]; unsigned* bs = Bs[0];
        *(uint4*)&as[ar * 20 + ac]        = make_uint4(f2tf(a0r.x), f2tf(a0r.y), f2tf(a0r.z), f2tf(a0r.w));
        *(uint4*)&as[(ar + 64) * 20 + ac] = make_uint4(f2tf(a1r.x), f2tf(a1r.y), f2tf(a1r.z), f2tf(a1r.w));
        *(uint4*)&bs[br * 136 + bc]       = make_uint4(f2tf(b0r.x), f2tf(b0r.y), f2tf(b0r.z), f2tf(b0r.w));
        *(uint4*)&bs[(br + 8) * 136 + bc] = make_uint4(f2tf(b1r.x), f2tf(b1r.y), f2tf(b1r.z), f2tf(b1r.w));
    }
    __syncthreads();

    for (int kt = 0; kt < NT; ++kt) {
        const int buf = kt & 1;
        if (kt + 1 < NT) {
            const float* Ap2 = Ap + (kt + 1) * 16;
            const float* Bp2 = Bp + (size_t)(kt + 1) * 16 * N;
            a0r = *(const float4*)Ap2;
            a1r = *(const float4*)(Ap2 + (size_t)64 * K);
            b0r = *(const float4*)Bp2;
            b1r = *(const float4*)(Bp2 + (size_t)8 * N);
        }
        const unsigned* as = As[buf];
        const unsigned* bs = Bs[buf];
#pragma unroll
        for (int ks = 0; ks < 16; ks += 8) {
            unsigned af[4][4], bf[4][2];
#pragma unroll
            for (int mt = 0; mt < 4; ++mt) {
                const int r = wm * 64 + mt * 16 + g;
                af[mt][0] = as[r * 20 + ks + tg];
                af[mt][1] = as[(r + 8) * 20 + ks + tg];
                af[mt][2] = as[r * 20 + ks + tg + 4];
                af[mt][3] = as[(r + 8) * 20 + ks + tg + 4];
            }
#pragma unroll
            for (int nt = 0; nt < 4; ++nt) {
                const int nc = wn * 32 + nt * 8 + g;
                bf[nt][0] = bs[(ks + tg) * 136 + nc];
                bf[nt][1] = bs[(ks + tg + 4) * 136 + nc];
            }
#pragma unroll
            for (int mt = 0; mt < 4; ++mt)
#pragma unroll
                for (int nt = 0; nt < 4; ++nt)
                    mma8(acc[mt][nt], af[mt], bf[nt]);
        }
        if (kt + 1 < NT) {
            unsigned* asw = As[buf ^ 1]; unsigned* bsw = Bs[buf ^ 1];
            *(uint4*)&asw[ar * 20 + ac]        = make_uint4(f2tf(a0r.x), f2tf(a0r.y), f2tf(a0r.z), f2tf(a0r.w));
            *(uint4*)&asw[(ar + 64) * 20 + ac] = make_uint4(f2tf(a1r.x), f2tf(a1r.y), f2tf(a1r.z), f2tf(a1r.w));
            *(uint4*)&bsw[br * 136 + bc]       = make_uint4(f2tf(b0r.x), f2tf(b0r.y), f2tf(b0r.z), f2tf(b0r.w));
            *(uint4*)&bsw[(br + 8) * 136 + bc] = make_uint4(f2tf(b1r.x), f2tf(b1r.y), f2tf(b1r.z), f2tf(b1r.w));
        }
        __syncthreads();
    }

#pragma unroll
    for (int mt = 0; mt < 4; ++mt) {
#pragma unroll
        for (int nt = 0; nt < 4; ++nt) {
            const int r0 = mBase + wm * 64 + mt * 16 + g;
            const int c0 = nBase + wn * 32 + nt * 8 + tg * 2;
            *(float2*)&C[(size_t)r0 * N + c0]       = make_float2(acc[mt][nt][0], acc[mt][nt][1]);
            *(float2*)&C[(size_t)(r0 + 8) * N + c0] = make_float2(acc[mt][nt][2], acc[mt][nt][3]);
        }
    }
}

__global__ void bias_kernel(const float* __restrict__ rpb) {
    int idx = blockIdx.x * 256 + threadIdx.x;
    if (idx >= NHEAD * NTOK * NTOK) return;
    int h = idx / (NTOK * NTOK);
    int r = idx % (NTOK * NTOK);
    int i = r / NTOK, j = r % NTOK;
    int rpi = 13 * ((i % 7) - (j % 7) + 6) + (i / 7) - (j / 7) + 6;
    g_bias[idx] = rpb[rpi * NHEAD + h];
}

// ---------------- tensor-core attention ----------------
// One CTA per (window b, head h), 128 threads = 4 warps, window padded 49->64.
// Warp w owns output rows [w*16, w*16+16): S = Q K^T (m16 n64 k32 per warp),
// bias+mask+softmax in registers (4-lane shfl reductions), P -> tf32 smem
// (aliases dead Q/K), O = P V (m16 n32 k64 per warp).
__global__ __launch_bounds__(128)
void attn_mma_kernel(const float* __restrict__ mask) {
    __shared__ unsigned smqk[2 * 64 * 36];   // qs | ks ; later aliased by ps (64*68 <= 2*64*36)
    __shared__ unsigned smv[64 * 36];

    unsigned* qs = smqk;
    unsigned* ks = smqk + 64 * 36;
    unsigned* ps = smqk;                     // alias (safe after __syncthreads post-MMA)
    unsigned* vs = smv;

    const int tid  = threadIdx.x;
    const int w    = tid >> 5;
    const int lane = tid & 31;
    const int g    = lane >> 2;
    const int tg   = lane & 3;
    const int m0   = w << 4;

    const int blk = blockIdx.x;
    const int b = blk / NHEAD;
    const int h = blk - b * NHEAD;

    const float* base = g_qkv + (size_t)b * NTOK * QKVDIM + h * HD;
    const float scale = 0.17677669529663687f;   // 32^-0.5

    // Load Q (scaled), K, V -> tf32 smem, zero-padded to 64 rows.
#pragma unroll
    for (int e = tid; e < 64 * 32; e += 128) {
        int n = e >> 5, d = e & 31;
        unsigned q = 0, k = 0, v = 0;
        if (n < NTOK) {
            size_t o = (size_t)n * QKVDIM + d;
            q = f2tf(base[o] * scale);
            k = f2tf(base[o + CDIM]);
            v = f2tf(base[o + 2 * CDIM]);
        }
        qs[n * 36 + d] = q;
        ks[n * 36 + d] = k;
        vs[n * 36 + d] = v;
    }
    __syncthreads();

    // S = Q K^T : per-warp m16 x n64, k=32
    float s[8][4];
#pragma unroll
    for (int nt = 0; nt < 8; ++nt)
#pragma unroll
        for (int q = 0; q < 4; ++q) s[nt][q] = 0.f;

#pragma unroll
    for (int k0 = 0; k0 < 32; k0 += 8) {
        unsigned af[4];
        af[0] = qs[(m0 + g) * 36 + k0 + tg];
        af[1] = qs[(m0 + g + 8) * 36 + k0 + tg];
        af[2] = qs[(m0 + g) * 36 + k0 + tg + 4];
        af[3] = qs[(m0 + g + 8) * 36 + k0 + tg + 4];
#pragma unroll
        for (int nt = 0; nt < 8; ++nt) {
            unsigned bf[2];
            bf[0] = ks[(nt * 8 + g) * 36 + k0 + tg];
            bf[1] = ks[(nt * 8 + g) * 36 + k0 + tg + 4];
            mma8(s[nt], af, bf);
        }
    }
    __syncthreads();   // qs/ks dead; ps may be written after this

    // Bias + mask (fragment form), softmax in registers.
    const int rA = m0 + g, rB = m0 + g + 8;
    const bool rAv = rA < NTOK, rBv = rB < NTOK;
    const float* bh = g_bias + h * NTOK * NTOK;
    const float* mw = mask + (size_t)(b & (NWMASK - 1)) * NTOK * NTOK;

#pragma unroll
    for (int nt = 0; nt < 8; ++nt) {
        int c = nt * 8 + tg * 2;
        if (c < NTOK) {
            if (rAv) s[nt][0] += bh[rA * NTOK + c] + mw[rA * NTOK + c];
            if (rBv) s[nt][2] += bh[rB * NTOK + c] + mw[rB * NTOK + c];
            if (c + 1 < NTOK) {
                if (rAv) s[nt][1] += bh[rA * NTOK + c + 1] + mw[rA * NTOK + c + 1];
                if (rBv) s[nt][3] += bh[rB * NTOK + c + 1] + mw[rB * NTOK + c + 1];
            }
        }
    }

    float mA = -3.4e38f, mB = -3.4e38f;
#pragma unroll
    for (int nt = 0; nt < 8; ++nt) {
        int c = nt * 8 + tg * 2;
        if (c < NTOK)     { mA = fmaxf(mA, s[nt][0]); mB = fmaxf(mB, s[nt][2]); }
        if (c + 1 < NTOK) { mA = fmaxf(mA, s[nt][1]); mB = fmaxf(mB, s[nt][3]); }
    }
    mA = fmaxf(mA, __shfl_xor_sync(0xffffffffu, mA, 1));
    mA = fmaxf(mA, __shfl_xor_sync(0xffffffffu, mA, 2));
    mB = fmaxf(mB, __shfl_xor_sync(0xffffffffu, mB, 1));
    mB = fmaxf(mB, __shfl_xor_sync(0xffffffffu, mB, 2));

    float sA = 0.f, sB = 0.f;
#pragma unroll
    for (int nt = 0; nt < 8; ++nt) {
        int c = nt * 8 + tg * 2;
        float e0 = (c     < NTOK) ? __expf(s[nt][0] - mA) : 0.f;
        float e1 = (c + 1 < NTOK) ? __expf(s[nt][1] - mA) : 0.f;
        float e2 = (c     < NTOK) ? __expf(s[nt][2] - mB) : 0.f;
        float e3 = (c + 1 < NTOK) ? __expf(s[nt][3] - mB) : 0.f;
        s[nt][0] = e0; s[nt][1] = e1; s[nt][2] = e2; s[nt][3] = e3;
        sA += e0 + e1;  sB += e2 + e3;
    }
    sA += __shfl_xor_sync(0xffffffffu, sA, 1);
    sA += __shfl_xor_sync(0xffffffffu, sA, 2);
    sB += __shfl_xor_sync(0xffffffffu, sB, 1);
    sB += __shfl_xor_sync(0xffffffffu, sB, 2);
    const float invA = 1.f / sA, invB = 1.f / sB;

    // P -> tf32 smem (stride 68: conflict-free A-frag reads)
#pragma unroll
    for (int nt = 0; nt < 8; ++nt) {
        int c = nt * 8 + tg * 2;
        if (rAv) *(uint2*)&ps[rA * 68 + c] = make_uint2(f2tf(s[nt][0] * invA), f2tf(s[nt][1] * invA));
        if (rBv) *(uint2*)&ps[rB * 68 + c] = make_uint2(f2tf(s[nt][2] * invB), f2tf(s[nt][3] * invB));
    }
    __syncwarp();   // each warp reads only its own 16 rows of ps

    // O = P V : per-warp m16 x n32, k=64
    float o[4][4];
#pragma unroll
    for (int nt = 0; nt < 4; ++nt)
#pragma unroll
        for (int q = 0; q < 4; ++q) o[nt][q] = 0.f;

#pragma unroll
    for (int k0 = 0; k0 < 64; k0 += 8) {
        unsigned af[4];
        af[0] = ps[(m0 + g) * 68 + k0 + tg];
        af[1] = ps[(m0 + g + 8) * 68 + k0 + tg];
        af[2] = ps[(m0 + g) * 68 + k0 + tg + 4];
        af[3] = ps[(m0 + g + 8) * 68 + k0 + tg + 4];
#pragma unroll
        for (int nt = 0; nt < 4; ++nt) {
            unsigned bf[2];
            bf[0] = vs[(k0 + tg) * 36 + nt * 8 + g];
            bf[1] = vs[(k0 + tg + 4) * 36 + nt * 8 + g];
            mma8(o[nt], af, bf);
        }
    }

    float* ob = g_att + (size_t)b * NTOK * CDIM + h * HD;
#pragma unroll
    for (int nt = 0; nt < 4; ++nt) {
        int c = nt * 8 + tg * 2;
        if (rAv) *(float2*)&ob[(size_t)rA * CDIM + c] = make_float2(o[nt][0], o[nt][1]);
        if (rBv) *(float2*)&ob[(size_t)rB * CDIM + c] = make_float2(o[nt][2], o[nt][3]);
    }
}

extern "C" void kernel_launch(void* const* d_in, const int* in_sizes, int n_in,
                              void* d_out, int out_size) {
    const float *x = nullptr, *mask = nullptr, *wqkv = nullptr, *wproj = nullptr, *rpb = nullptr;
    for (int i = 0; i < n_in; ++i) {
        switch (in_sizes[i]) {
            case 154140672: x     = (const float*)d_in[i]; break;  // 401408*384
            case 2458624:   mask  = (const float*)d_in[i]; break;  // 1024*49*49
            case 442368:    wqkv  = (const float*)d_in[i]; break;  // 384*1152
            case 147456:    wproj = (const float*)d_in[i]; break;  // 384*384
            case 2028:      rpb   = (const float*)d_in[i]; break;  // 169*12
        }
    }

    float *qkv_p = nullptr, *att_p = nullptr;
    cudaGetSymbolAddress((void**)&qkv_p, g_qkv);
    cudaGetSymbolAddress((void**)&att_p, g_att);

    bias_kernel<<<(NHEAD * NTOK * NTOK + 255) / 256, 256>>>(rpb);

    // QKV projection: [401408,384] @ [384,1152]
    gemm_tf32<<<dim3(QKVDIM / 128, MROWS / 128), 256>>>(x, wqkv, qkv_p, QKVDIM, CDIM);

    // Tensor-core per-(window, head) attention
    attn_mma_kernel<<<BWIN * NHEAD, 128>>>(mask);

    // Output projection: [401408,384] @ [384,384] -> d_out
    gemm_tf32<<<dim3(CDIM / 128, MROWS / 128), 256>>>(att_p, wproj, (float*)d_out, CDIM, CDIM);
}

// round 7
// speedup vs baseline: 1.6342x; 1.0187x over previous
#include <cuda_runtime.h>

#define NTOK 49
#define NHEAD 12
#define HD 32
#define CDIM 384
#define QKVDIM 1152
#define BWIN 8192
#define NWMASK 1024
#define MROWS (BWIN * NTOK)   // 401408

__device__ float g_qkv[(size_t)MROWS * QKVDIM];     // QKV GEMM output
__device__ float g_att[(size_t)MROWS * CDIM];       // pre-projection attention output
__device__ float g_bias[NHEAD * NTOK * NTOK];       // [H, N, N] relative position bias

__device__ __forceinline__ unsigned f2tf(float f) {
    unsigned r;
    asm("cvt.rna.tf32.f32 %0, %1;" : "=r"(r) : "f"(f));
    return r;
}

__device__ __forceinline__ void mma8(float* c, const unsigned* a, const unsigned* b) {
    asm volatile(
        "mma.sync.aligned.m16n8k8.row.col.f32.tf32.tf32.f32 "
        "{%0,%1,%2,%3}, {%4,%5,%6,%7}, {%8,%9}, {%0,%1,%2,%3};\n"
        : "+f"(c[0]), "+f"(c[1]), "+f"(c[2]), "+f"(c[3])
        : "r"(a[0]), "r"(a[1]), "r"(a[2]), "r"(a[3]), "r"(b[0]), "r"(b[1]));
}

__device__ __forceinline__ void cpasync16(unsigned saddr, const void* g) {
    asm volatile("cp.async.cg.shared.global [%0], [%1], 16;\n" :: "r"(saddr), "l"(g));
}
__device__ __forceinline__ void cp_commit() { asm volatile("cp.async.commit_group;\n"); }
__device__ __forceinline__ void cp_wait0()  { asm volatile("cp.async.wait_group 0;\n"); }

// ---------------- big GEMMs: cp.async staging (raw fp32), cvt at frag load ----------------
// C[M,N] = A[M,K] @ B[K,N]; tf32 tensor-core compute (cvt.rna post-LDS: numerics
// identical to cvt-at-store). 2-stage cp.async ring, 2 CTAs/SM.
__global__ __launch_bounds__(256, 2)
void gemm_tf32(const float* __restrict__ A, const float* __restrict__ B,
               float* __restrict__ C, int N, int K) {
    __shared__ float As[2][128 * 20];   // [m][k], stride 20 -> conflict-free frag LDS
    __shared__ float Bs[2][16 * 136];   // [k][n], stride 136 -> conflict-free frag LDS

    const int t    = threadIdx.x;
    const int lane = t & 31;
    const int w    = t >> 5;
    const int wm   = w & 1;        // 2 warp-rows (64 M each)
    const int wn   = w >> 1;       // 4 warp-cols (32 N each)
    const int g    = lane >> 2;
    const int tg   = lane & 3;
    const int mBase = blockIdx.y << 7;
    const int nBase = blockIdx.x << 7;

    // staging thread map: A tile 128x16 (4 thr/row, 16B each, x2 rows), B tile 16x128
    const int ar = t >> 2,  ac = (t & 3) << 2;
    const int br = t >> 5,  bc = lane << 2;

    const float* Ap = A + (size_t)(mBase + ar) * K + ac;
    const float* Bp = B + (size_t)br * N + nBase + bc;

    const unsigned sA0 = (unsigned)__cvta_generic_to_shared(&As[0][ar * 20 + ac]);
    const unsigned sA1 = (unsigned)__cvta_generic_to_shared(&As[0][(ar + 64) * 20 + ac]);
    const unsigned sB0 = (unsigned)__cvta_generic_to_shared(&Bs[0][br * 136 + bc]);
    const unsigned sB1 = (unsigned)__cvta_generic_to_shared(&Bs[0][(br + 8) * 136 + bc]);
    const unsigned aStride = 128 * 20 * 4;   // bytes between stages
    const unsigned bStride = 16 * 136 * 4;

    float acc[4][4][4];
#pragma unroll
    for (int i = 0; i < 4; ++i)
#pragma unroll
        for (int j = 0; j < 4; ++j)
#pragma unroll
            for (int q = 0; q < 4; ++q) acc[i][j][q] = 0.f;

    const int NT = K >> 4;

    // prologue: stage tile 0
    cpasync16(sA0, Ap);
    cpasync16(sA1, Ap + (size_t)64 * K);
    cpasync16(sB0, Bp);
    cpasync16(sB1, Bp + (size_t)8 * N);
    cp_commit();

    for (int kt = 0; kt < NT; ++kt) {
        const int buf = kt & 1;
        cp_wait0();
        __syncthreads();

        if (kt + 1 < NT) {   // issue next tile into other buffer; overlaps this tile's math
            const unsigned so = (buf ^ 1) ? aStride : 0u;
            const unsigned sob = (buf ^ 1) ? bStride : 0u;
            const float* Ap2 = Ap + (kt + 1) * 16;
            const float* Bp2 = Bp + (size_t)(kt + 1) * 16 * N;
            cpasync16(sA0 + so, Ap2);
            cpasync16(sA1 + so, Ap2 + (size_t)64 * K);
            cpasync16(sB0 + sob, Bp2);
            cpasync16(sB1 + sob, Bp2 + (size_t)8 * N);
            cp_commit();
        }

        const float* as = As[buf];
        const float* bs = Bs[buf];
#pragma unroll
        for (int ks = 0; ks < 16; ks += 8) {
            unsigned af[4][4], bf[4][2];
#pragma unroll
            for (int mt = 0; mt < 4; ++mt) {
                const int r = wm * 64 + mt * 16 + g;
                af[mt][0] = f2tf(as[r * 20 + ks + tg]);
                af[mt][1] = f2tf(as[(r + 8) * 20 + ks + tg]);
                af[mt][2] = f2tf(as[r * 20 + ks + tg + 4]);
                af[mt][3] = f2tf(as[(r + 8) * 20 + ks + tg + 4]);
            }
#pragma unroll
            for (int nt = 0; nt < 4; ++nt) {
                const int nc = wn * 32 + nt * 8 + g;
                bf[nt][0] = f2tf(bs[(ks + tg) * 136 + nc]);
                bf[nt][1] = f2tf(bs[(ks + tg + 4) * 136 + nc]);
            }
#pragma unroll
            for (int mt = 0; mt < 4; ++mt)
#pragma unroll
                for (int nt = 0; nt < 4; ++nt)
                    mma8(acc[mt][nt], af[mt], bf[nt]);
        }
        __syncthreads();   // all warps done with buf before next iter's cp overwrites peer buf
    }

#pragma unroll
    for (int mt = 0; mt < 4; ++mt) {
#pragma unroll
        for (int nt = 0; nt < 4; ++nt) {
            const int r0 = mBase + wm * 64 + mt * 16 + g;
            const int c0 = nBase + wn * 32 + nt * 8 + tg * 2;
            *(float2*)&C[(size_t)r0 * N + c0]       = make_float2(acc[mt][nt][0], acc[mt][nt][1]);
            *(float2*)&C[(size_t)(r0 + 8) * N + c0] = make_float2(acc[mt][nt][2], acc[mt][nt][3]);
        }
    }
}

__global__ void bias_kernel(const float* __restrict__ rpb) {
    int idx = blockIdx.x * 256 + threadIdx.x;
    if (idx >= NHEAD * NTOK * NTOK) return;
    int h = idx / (NTOK * NTOK);
    int r = idx % (NTOK * NTOK);
    int i = r / NTOK, j = r % NTOK;
    int rpi = 13 * ((i % 7) - (j % 7) + 6) + (i / 7) - (j / 7) + 6;
    g_bias[idx] = rpb[rpi * NHEAD + h];
}

// ---------------- tensor-core attention (unchanged from round 4) ----------------
__global__ __launch_bounds__(128)
void attn_mma_kernel(const float* __restrict__ mask) {
    __shared__ unsigned smqk[2 * 64 * 36];
    __shared__ unsigned smv[64 * 36];

    unsigned* qs = smqk;
    unsigned* ks = smqk + 64 * 36;
    unsigned* ps = smqk;                     // alias (safe after post-MMA sync)
    unsigned* vs = smv;

    const int tid  = threadIdx.x;
    const int w    = tid >> 5;
    const int lane = tid & 31;
    const int g    = lane >> 2;
    const int tg   = lane & 3;
    const int m0   = w << 4;

    const int blk = blockIdx.x;
    const int b = blk / NHEAD;
    const int h = blk - b * NHEAD;

    const float* base = g_qkv + (size_t)b * NTOK * QKVDIM + h * HD;
    const float scale = 0.17677669529663687f;

#pragma unroll
    for (int e = tid; e < 64 * 32; e += 128) {
        int n = e >> 5, d = e & 31;
        unsigned q = 0, k = 0, v = 0;
        if (n < NTOK) {
            size_t o = (size_t)n * QKVDIM + d;
            q = f2tf(base[o] * scale);
            k = f2tf(base[o + CDIM]);
            v = f2tf(base[o + 2 * CDIM]);
        }
        qs[n * 36 + d] = q;
        ks[n * 36 + d] = k;
        vs[n * 36 + d] = v;
    }
    __syncthreads();

    float s[8][4];
#pragma unroll
    for (int nt = 0; nt < 8; ++nt)
#pragma unroll
        for (int q = 0; q < 4; ++q) s[nt][q] = 0.f;

#pragma unroll
    for (int k0 = 0; k0 < 32; k0 += 8) {
        unsigned af[4];
        af[0] = qs[(m0 + g) * 36 + k0 + tg];
        af[1] = qs[(m0 + g + 8) * 36 + k0 + tg];
        af[2] = qs[(m0 + g) * 36 + k0 + tg + 4];
        af[3] = qs[(m0 + g + 8) * 36 + k0 + tg + 4];
#pragma unroll
        for (int nt = 0; nt < 8; ++nt) {
            unsigned bf[2];
            bf[0] = ks[(nt * 8 + g) * 36 + k0 + tg];
            bf[1] = ks[(nt * 8 + g) * 36 + k0 + tg + 4];
            mma8(s[nt], af, bf);
        }
    }
    __syncthreads();

    const int rA = m0 + g, rB = m0 + g + 8;
    const bool rAv = rA < NTOK, rBv = rB < NTOK;
    const float* bh = g_bias + h * NTOK * NTOK;
    const float* mw = mask + (size_t)(b & (NWMASK - 1)) * NTOK * NTOK;

#pragma unroll
    for (int nt = 0; nt < 8; ++nt) {
        int c = nt * 8 + tg * 2;
        if (c < NTOK) {
            if (rAv) s[nt][0] += bh[rA * NTOK + c] + mw[rA * NTOK + c];
            if (rBv) s[nt][2] += bh[rB * NTOK + c] + mw[rB * NTOK + c];
            if (c + 1 < NTOK) {
                if (rAv) s[nt][1] += bh[rA * NTOK + c + 1] + mw[rA * NTOK + c + 1];
                if (rBv) s[nt][3] += bh[rB * NTOK + c + 1] + mw[rB * NTOK + c + 1];
            }
        }
    }

    float mA = -3.4e38f, mB = -3.4e38f;
#pragma unroll
    for (int nt = 0; nt < 8; ++nt) {
        int c = nt * 8 + tg * 2;
        if (c < NTOK)     { mA = fmaxf(mA, s[nt][0]); mB = fmaxf(mB, s[nt][2]); }
        if (c + 1 < NTOK) { mA = fmaxf(mA, s[nt][1]); mB = fmaxf(mB, s[nt][3]); }
    }
    mA = fmaxf(mA, __shfl_xor_sync(0xffffffffu, mA, 1));
    mA = fmaxf(mA, __shfl_xor_sync(0xffffffffu, mA, 2));
    mB = fmaxf(mB, __shfl_xor_sync(0xffffffffu, mB, 1));
    mB = fmaxf(mB, __shfl_xor_sync(0xffffffffu, mB, 2));

    float sA = 0.f, sB = 0.f;
#pragma unroll
    for (int nt = 0; nt < 8; ++nt) {
        int c = nt * 8 + tg * 2;
        float e0 = (c     < NTOK) ? __expf(s[nt][0] - mA) : 0.f;
        float e1 = (c + 1 < NTOK) ? __expf(s[nt][1] - mA) : 0.f;
        float e2 = (c     < NTOK) ? __expf(s[nt][2] - mB) : 0.f;
        float e3 = (c + 1 < NTOK) ? __expf(s[nt][3] - mB) : 0.f;
        s[nt][0] = e0; s[nt][1] = e1; s[nt][2] = e2; s[nt][3] = e3;
        sA += e0 + e1;  sB += e2 + e3;
    }
    sA += __shfl_xor_sync(0xffffffffu, sA, 1);
    sA += __shfl_xor_sync(0xffffffffu, sA, 2);
    sB += __shfl_xor_sync(0xffffffffu, sB, 1);
    sB += __shfl_xor_sync(0xffffffffu, sB, 2);
    const float invA = 1.f / sA, invB = 1.f / sB;

#pragma unroll
    for (int nt = 0; nt < 8; ++nt) {
        int c = nt * 8 + tg * 2;
        if (rAv) *(uint2*)&ps[rA * 68 + c] = make_uint2(f2tf(s[nt][0] * invA), f2tf(s[nt][1] * invA));
        if (rBv) *(uint2*)&ps[rB * 68 + c] = make_uint2(f2tf(s[nt][2] * invB), f2tf(s[nt][3] * invB));
    }
    __syncwarp();

    float o[4][4];
#pragma unroll
    for (int nt = 0; nt < 4; ++nt)
#pragma unroll
        for (int q = 0; q < 4; ++q) o[nt][q] = 0.f;

#pragma unroll
    for (int k0 = 0; k0 < 64; k0 += 8) {
        unsigned af[4];
        af[0] = ps[(m0 + g) * 68 + k0 + tg];
        af[1] = ps[(m0 + g + 8) * 68 + k0 + tg];
        af[2] = ps[(m0 + g) * 68 + k0 + tg + 4];
        af[3] = ps[(m0 + g + 8) * 68 + k0 + tg + 4];
#pragma unroll
        for (int nt = 0; nt < 4; ++nt) {
            unsigned bf[2];
            bf[0] = vs[(k0 + tg) * 36 + nt * 8 + g];
            bf[1] = vs[(k0 + tg + 4) * 36 + nt * 8 + g];
            mma8(o[nt], af, bf);
        }
    }

    float* ob = g_att + (size_t)b * NTOK * CDIM + h * HD;
#pragma unroll
    for (int nt = 0; nt < 4; ++nt) {
        int c = nt * 8 + tg * 2;
        if (rAv) *(float2*)&ob[(size_t)rA * CDIM + c] = make_float2(o[nt][0], o[nt][1]);
        if (rBv) *(float2*)&ob[(size_t)rB * CDIM + c] = make_float2(o[nt][2], o[nt][3]);
    }
}

extern "C" void kernel_launch(void* const* d_in, const int* in_sizes, int n_in,
                              void* d_out, int out_size) {
    const float *x = nullptr, *mask = nullptr, *wqkv = nullptr, *wproj = nullptr, *rpb = nullptr;
    for (int i = 0; i < n_in; ++i) {
        switch (in_sizes[i]) {
            case 154140672: x     = (const float*)d_in[i]; break;  // 401408*384
            case 2458624:   mask  = (const float*)d_in[i]; break;  // 1024*49*49
            case 442368:    wqkv  = (const float*)d_in[i]; break;  // 384*1152
            case 147456:    wproj = (const float*)d_in[i]; break;  // 384*384
            case 2028:      rpb   = (const float*)d_in[i]; break;  // 169*12
        }
    }

    float *qkv_p = nullptr, *att_p = nullptr;
    cudaGetSymbolAddress((void**)&qkv_p, g_qkv);
    cudaGetSymbolAddress((void**)&att_p, g_att);

    bias_kernel<<<(NHEAD * NTOK * NTOK + 255) / 256, 256>>>(rpb);

    // QKV projection: [401408,384] @ [384,1152]
    gemm_tf32<<<dim3(QKVDIM / 128, MROWS / 128), 256>>>(x, wqkv, qkv_p, QKVDIM, CDIM);

    // Tensor-core per-(window, head) attention
    attn_mma_kernel<<<BWIN * NHEAD, 128>>>(mask);

    // Output projection: [401408,384] @ [384,384] -> d_out
    gemm_tf32<<<dim3(CDIM / 128, MROWS / 128), 256>>>(att_p, wproj, (float*)d_out, CDIM, CDIM);
}